// round 12
// baseline (speedup 1.0000x reference)
#include <cuda_runtime.h>
#include <cuda_fp16.h>
#include <cstdint>

// ---------------- problem constants ----------------
#define Bb   2
#define Ss   4096
#define Dd   2048
#define Hh   16
#define DH   8192
#define Ll   512
#define NSEGc 8
#define BSr  (Bb*Ss)
#define BHn  (Bb*Hh)

// ---------------- scratch ----------------
__device__ float g_h2 [(size_t)BSr*Dd];
__device__ __half g_x_h  [(size_t)BSr*Dd];
__device__ __half g_q_h  [(size_t)BSr*Dd];
__device__ __half g_k_h  [(size_t)BSr*Dd];
__device__ __half g_v_h  [(size_t)BSr*Dd];
__device__ __half g_sq_h [(size_t)BSr*Dd];
__device__ __half g_sk_h [(size_t)BSr*Dd];
__device__ __half g_dot_h[(size_t)BSr*Dd];
__device__ __half g_att_h[(size_t)BSr*Dd];
__device__ __half g_a_h  [(size_t)BSr*Dd];
__device__ __half g_h1_h [(size_t)BSr*DH];
__device__ __half g_wqkv[(size_t)3*Dd*Dd];
__device__ __half g_wo[(size_t)Dd*Dd];
__device__ __half g_w1[(size_t)DH*Dd];
__device__ __half g_w2[(size_t)Dd*DH];
__device__ float  g_mem32[64 * 8192];

// ---------------- helpers ----------------
__device__ __forceinline__ float gelu_exact(float x) {
    return 0.5f * x * (1.0f + erff(x * 0.70710678118654752440f));
}
__device__ __forceinline__ float elu1(float x) {
    return (x > 0.0f) ? (x + 1.0f) : __expf(x);
}
__device__ __forceinline__ uint32_t smem_u32(const void* p) {
    uint32_t a;
    asm("{ .reg .u64 t; cvta.to.shared.u64 t, %1; cvt.u32.u64 %0, t; }" : "=r"(a) : "l"(p));
    return a;
}
__device__ __forceinline__ void mma16816(float* c, const uint32_t* a, const uint32_t* b) {
    asm volatile(
        "mma.sync.aligned.m16n8k16.row.col.f32.f16.f16.f32 "
        "{%0,%1,%2,%3}, {%4,%5,%6,%7}, {%8,%9}, {%0,%1,%2,%3};"
        : "+f"(c[0]), "+f"(c[1]), "+f"(c[2]), "+f"(c[3])
        : "r"(a[0]), "r"(a[1]), "r"(a[2]), "r"(a[3]), "r"(b[0]), "r"(b[1]));
}
__device__ __forceinline__ void ldsm4(uint32_t addr, uint32_t* r) {
    asm volatile("ldmatrix.sync.aligned.m8n8.x4.shared.b16 {%0,%1,%2,%3}, [%4];"
                 : "=r"(r[0]), "=r"(r[1]), "=r"(r[2]), "=r"(r[3]) : "r"(addr));
}
__device__ __forceinline__ void ldsm4t(uint32_t addr, uint32_t* r) {
    asm volatile("ldmatrix.sync.aligned.m8n8.x4.trans.shared.b16 {%0,%1,%2,%3}, [%4];"
                 : "=r"(r[0]), "=r"(r[1]), "=r"(r[2]), "=r"(r[3]) : "r"(addr));
}
__device__ __forceinline__ void cp_async16(uint32_t saddr, const void* gaddr) {
    asm volatile("cp.async.cg.shared.global [%0], [%1], 16;" :: "r"(saddr), "l"(gaddr));
}
#define CP_COMMIT() asm volatile("cp.async.commit_group;" ::: "memory")
#define CP_WAIT1()  asm volatile("cp.async.wait_group 1;" ::: "memory")
#define CP_WAIT0()  asm volatile("cp.async.wait_group 0;" ::: "memory")

__device__ __forceinline__ uint32_t aswz(int row, int chunk) {
    return (uint32_t)(row * 128 + ((chunk ^ (row & 7)) << 4));
}
__device__ __forceinline__ uint32_t swzh(int row, int chunk16) {
    return (uint32_t)(row * 256 + ((chunk16 ^ (row & 7)) << 4));
}

// ---------------- weights convert+transpose + x convert ----------------
__global__ void __launch_bounds__(256)
convt_all(const float* __restrict__ x, __half* __restrict__ xh,
          const float* __restrict__ Wq, const float* __restrict__ Wk,
          const float* __restrict__ Wv, const float* __restrict__ Wo,
          const float* __restrict__ W1, const float* __restrict__ W2,
          __half* tqkv, __half* to_, __half* t1, __half* t2)
{
    const int id = blockIdx.x;
    const int tid = threadIdx.x;
    if (id >= 12288) {
        size_t base4 = (size_t)(id - 12288) * 1024;
#pragma unroll
        for (int j = 0; j < 4; j++) {
            size_t i4 = base4 + tid + j * 256;
            float4 v = ((const float4*)x)[i4];
            __half2 a, b;
            a.x = __float2half_rn(v.x); a.y = __float2half_rn(v.y);
            b.x = __float2half_rn(v.z); b.y = __float2half_rn(v.w);
            ((__half2*)xh)[i4*2]   = a;
            ((__half2*)xh)[i4*2+1] = b;
        }
        return;
    }
    const float* W; __half* T; int K, N, nb, kb;
    if (id < 4096) {
        int w = id >> 10, t = id & 1023;
        nb = t & 31; kb = t >> 5; K = 2048; N = 2048;
        if (w < 3)  { W = (w == 0) ? Wq : (w == 1) ? Wk : Wv; T = tqkv + (size_t)w * 4194304; }
        else        { W = Wo; T = to_; }
    } else if (id < 8192) {
        int t = id - 4096; nb = t & 127; kb = t >> 7; K = 2048; N = 8192;
        W = W1; T = t1;
    } else {
        int t = id - 8192; nb = t & 31; kb = t >> 5; K = 8192; N = 2048;
        W = W2; T = t2;
    }
    __shared__ float tbuf[64][65];
    const int n0 = nb * 64, k0 = kb * 64;
#pragma unroll
    for (int t = 0; t < 4; t++) {
        int i = tid + t * 256;
        int r = i >> 4, c4 = (i & 15) * 4;
        float4 v = *(const float4*)(W + (size_t)(k0 + r) * N + n0 + c4);
        tbuf[r][c4+0] = v.x; tbuf[r][c4+1] = v.y;
        tbuf[r][c4+2] = v.z; tbuf[r][c4+3] = v.w;
    }
    __syncthreads();
#pragma unroll
    for (int t = 0; t < 2; t++) {
        int i = tid + t * 256;
        int rn = i >> 3, kg = i & 7;
        __half tmp[8];
#pragma unroll
        for (int j = 0; j < 8; j++) tmp[j] = __float2half_rn(tbuf[kg*8 + j][rn]);
        *(uint4*)(T + (size_t)(n0 + rn) * K + k0 + kg * 8) = *(uint4*)tmp;
    }
}

// ---------------- GEMM core: 256x128 CTA tile, warp 64x64, BK=64, 3-stage ----------------
#define GEMM_STAGE_A 32768                 // 256 rows x 128B
#define GEMM_STAGE_B 16384                 // 128 rows x 128B
#define GEMM_STAGE_BYTES (GEMM_STAGE_A + GEMM_STAGE_B)
#define GEMM_SMEM_BYTES  (3 * GEMM_STAGE_BYTES)   // 147456

template<typename EpiF>
__device__ __forceinline__ void gemm_body(
    const __half* __restrict__ A, const __half* __restrict__ Bp,
    int M, int N, int K, uint32_t smem, EpiF epi)
{
    const int tid  = threadIdx.x;
    const int lane = tid & 31;
    const int w    = tid >> 5;
    const int wm   = w >> 1;           // 0..3 (64 rows each)
    const int wn   = w & 1;            // 0..1 (64 cols each)
    const size_t bm = (size_t)blockIdx.y * 256;
    const size_t bn = (size_t)blockIdx.x * 128;
    const int KT = K >> 6;

    const int a_row0 = wm * 64 + (lane & 7) + ((lane >> 3) & 1) * 8;
    const int a_ch   = (lane >> 4) & 1;
    const int b_row0 = wn * 64 + (lane & 7) + ((lane >> 4) & 1) * 8;
    const int b_ch   = (lane >> 3) & 1;

    const int rr = tid >> 3, cc = tid & 7;

    float acc[4][8][4];
#pragma unroll
    for (int i = 0; i < 4; i++)
#pragma unroll
        for (int j = 0; j < 8; j++)
#pragma unroll
            for (int q = 0; q < 4; q++) acc[i][j][q] = 0.0f;

    auto load_stage = [&](int st, int itk) {
        const uint32_t sa = smem + st * GEMM_STAGE_BYTES;
        const uint32_t sb = sa + GEMM_STAGE_A;
        const size_t k0 = (size_t)itk * 64;
#pragma unroll
        for (int t = 0; t < 8; t++) {
            int row = rr + t * 32;
            cp_async16(sa + aswz(row, cc), A + (bm + row) * (size_t)K + k0 + cc * 8);
        }
#pragma unroll
        for (int t = 0; t < 4; t++) {
            int row = rr + t * 32;
            cp_async16(sb + aswz(row, cc), Bp + (bn + row) * (size_t)K + k0 + cc * 8);
        }
    };

    load_stage(0, 0); CP_COMMIT();
    load_stage(1, 1); CP_COMMIT();

    int cur = 0;
    for (int it = 0; it < KT; it++) {
        CP_WAIT1();
        __syncthreads();
        int nxt = cur + 2; if (nxt >= 3) nxt -= 3;
        if (it + 2 < KT) load_stage(nxt, it + 2);
        CP_COMMIT();

        const uint32_t sa = smem + cur * GEMM_STAGE_BYTES;
        const uint32_t sb = sa + GEMM_STAGE_A;
#pragma unroll
        for (int ks = 0; ks < 4; ks++) {
            uint32_t ah[4][4];
#pragma unroll
            for (int mi = 0; mi < 4; mi++)
                ldsm4(sa + aswz(a_row0 + mi * 16, ks * 2 + a_ch), ah[mi]);
            uint32_t bh[8][2];
#pragma unroll
            for (int nt = 0; nt < 4; nt++) {
                uint32_t t4[4];
                ldsm4(sb + aswz(b_row0 + nt * 16, ks * 2 + b_ch), t4);
                bh[2*nt][0] = t4[0]; bh[2*nt][1] = t4[1];
                bh[2*nt+1][0] = t4[2]; bh[2*nt+1][1] = t4[3];
            }
#pragma unroll
            for (int mi = 0; mi < 4; mi++)
#pragma unroll
                for (int ni = 0; ni < 8; ni++)
                    mma16816(acc[mi][ni], ah[mi], bh[ni]);
        }
        cur = cur + 1; if (cur >= 3) cur -= 3;
    }

    const int rl = lane >> 2, cl = (lane & 3) * 2;
#pragma unroll
    for (int mi = 0; mi < 4; mi++)
#pragma unroll
        for (int ni = 0; ni < 8; ni++) {
            size_t row0 = bm + wm * 64 + mi * 16 + rl;
            size_t col  = bn + wn * 64 + ni * 8 + cl;
            epi(acc[mi][ni], row0, col);
        }
}

template<int EPI>
__global__ void __launch_bounds__(256, 1)
gemm_mma(const __half* __restrict__ A, const __half* __restrict__ Bp,
         const float* __restrict__ bias,
         float* __restrict__ Cf, __half* __restrict__ Ch, int M, int N, int K)
{
    extern __shared__ char sm_raw[];
    gemm_body(A, Bp, M, N, K, smem_u32(sm_raw),
        [&](const float* c, size_t row0, size_t col) {
            const float b0 = bias[col], b1 = bias[col + 1];
            float v00 = c[0] + b0, v01 = c[1] + b1;
            float v10 = c[2] + b0, v11 = c[3] + b1;
            if (EPI == 2) {
                v00 = gelu_exact(v00); v01 = gelu_exact(v01);
                v10 = gelu_exact(v10); v11 = gelu_exact(v11);
            }
            if (EPI == 0) {
                *(float2*)(Cf + row0 * (size_t)N + col)       = make_float2(v00, v01);
                *(float2*)(Cf + (row0 + 8) * (size_t)N + col) = make_float2(v10, v11);
            } else {
                __half2 p0, p1;
                p0.x = __float2half_rn(v00); p0.y = __float2half_rn(v01);
                p1.x = __float2half_rn(v10); p1.y = __float2half_rn(v11);
                *(__half2*)(Ch + row0 * (size_t)N + col)       = p0;
                *(__half2*)(Ch + (row0 + 8) * (size_t)N + col) = p1;
            }
        });
}

__global__ void __launch_bounds__(256, 1)
gemm_qkv(const __half* __restrict__ A, const __half* __restrict__ Bp,
         const float* __restrict__ bq, const float* __restrict__ bk,
         const float* __restrict__ bv,
         __half* __restrict__ qh, __half* __restrict__ kh, __half* __restrict__ vh,
         __half* __restrict__ sqh, __half* __restrict__ skh, int M, int K)
{
    extern __shared__ char sm_raw[];
    const int sel = (int)(blockIdx.x >> 4);
    const float* bias = (sel == 0) ? bq : (sel == 1) ? bk : bv;
    __half* outp = (sel == 0) ? qh : (sel == 1) ? kh : vh;
    __half* sigp = (sel == 0) ? sqh : (sel == 1) ? skh : nullptr;

    gemm_body(A, Bp, M, 6144, K, smem_u32(sm_raw),
        [&](const float* c, size_t row0, size_t col) {
            size_t lc = col & 2047;
            const float b0 = bias[lc], b1 = bias[lc + 1];
            float v00 = c[0] + b0, v01 = c[1] + b1;
            float v10 = c[2] + b0, v11 = c[3] + b1;
            __half2 p0, p1;
            p0.x = __float2half_rn(v00); p0.y = __float2half_rn(v01);
            p1.x = __float2half_rn(v10); p1.y = __float2half_rn(v11);
            *(__half2*)(outp + row0 * (size_t)Dd + lc)       = p0;
            *(__half2*)(outp + (row0 + 8) * (size_t)Dd + lc) = p1;
            if (sel < 2) {
                __half2 s0, s1;
                s0.x = __float2half_rn(elu1(v00)); s0.y = __float2half_rn(elu1(v01));
                s1.x = __float2half_rn(elu1(v10)); s1.y = __float2half_rn(elu1(v11));
                *(__half2*)(sigp + row0 * (size_t)Dd + lc)       = s0;
                *(__half2*)(sigp + (row0 + 8) * (size_t)Dd + lc) = s1;
            }
        });
}

// ---------------- fused attention (2 CTAs/SM) ----------------
#define FU_SMEM 98304
// local (flash) layout
#define LQ  0
#define LK0 16384
#define LK1 32768
#define LV0 49152
#define LV1 65536
#define LP  81920
// state layout
#define SBUF   16384
#define SBUFSZ 40960
#define SOFF_SQ 0
#define SOFF_SK 16384
#define SOFF_V  32768

// ----- local path: flash-style single pass (online softmax) -----
__device__ void attn_local_flash(const __half* __restrict__ q, const __half* __restrict__ k,
                                 const __half* __restrict__ v, __half* __restrict__ dot,
                                 char* sma, int rb, int seg, int bh)
{
    const uint32_t s_q = smem_u32(sma);
    const uint32_t s_k[2] = { s_q + LK0, s_q + LK1 };
    const uint32_t s_v[2] = { s_q + LV0, s_q + LV1 };
    const uint32_t s_p = s_q + LP;
    __shared__ float m_s[64], l_s[64], alpha_s[64], wmax[64][4], wsum[64][4];

    const int tid = threadIdx.x;
    const int lane = tid & 31;
    const int w = tid >> 5;
    const int wm = w >> 2;
    const int wn = w & 3;
    const int b = bh >> 4, h = bh & 15;
    const int r0 = rb * 64;
    const size_t rowbase = (size_t)(b * Ss + seg * Ll);
    const int colbase = h * 128;
    const int rl = lane >> 2, cl = (lane & 3) * 2;
    const float scale = 0.088388347648318447f;

    if (tid < 64) { m_s[tid] = -1e30f; l_s[tid] = 0.0f; }

    auto load_kv = [&](int ch) {
        const uint32_t kd = s_k[ch & 1], vd = s_v[ch & 1];
#pragma unroll
        for (int t = 0; t < 4; t++) {
            int idx = tid + t * 256, row = idx >> 4, c = idx & 15;
            size_t g = (rowbase + ch * 64 + row) * Dd + colbase + c * 8;
            cp_async16(kd + swzh(row, c), k + g);
            cp_async16(vd + swzh(row, c), v + g);
        }
    };

#pragma unroll
    for (int t = 0; t < 4; t++) {
        int idx = tid + t * 256, row = idx >> 4, c = idx & 15;
        cp_async16(s_q + swzh(row, c), q + (rowbase + r0 + row) * Dd + colbase + c * 8);
    }
    load_kv(0); CP_COMMIT();
    if (rb >= 1) load_kv(1);
    CP_COMMIT();

    float accd[2][4][4];
#pragma unroll
    for (int i = 0; i < 2; i++)
#pragma unroll
        for (int j = 0; j < 4; j++)
#pragma unroll
            for (int qq = 0; qq < 4; qq++) accd[i][j][qq] = 0.0f;

    for (int ch = 0; ch <= rb; ch++) {
        CP_WAIT1();
        __syncthreads();
        const uint32_t kb = s_k[ch & 1], vb = s_v[ch & 1];

        float accs[2][2][4];
#pragma unroll
        for (int i = 0; i < 2; i++)
#pragma unroll
            for (int j = 0; j < 2; j++)
#pragma unroll
                for (int qq = 0; qq < 4; qq++) accs[i][j][qq] = 0.0f;
#pragma unroll
        for (int ks = 0; ks < 8; ks++) {
            uint32_t a[2][4];
#pragma unroll
            for (int mi = 0; mi < 2; mi++) {
                int arow = wm*32 + mi*16 + (lane & 7) + ((lane >> 3) & 1) * 8;
                int ach  = ks*2 + ((lane >> 4) & 1);
                ldsm4(s_q + swzh(arow, ach), a[mi]);
            }
            uint32_t t4[4];
            int brow = wn*16 + (lane & 7) + ((lane >> 4) & 1) * 8;
            int bch  = ks*2 + ((lane >> 3) & 1);
            ldsm4(kb + swzh(brow, bch), t4);
            uint32_t b0[2] = {t4[0], t4[1]}, b1[2] = {t4[2], t4[3]};
#pragma unroll
            for (int mi = 0; mi < 2; mi++) {
                mma16816(accs[mi][0], a[mi], b0);
                mma16816(accs[mi][1], a[mi], b1);
            }
        }
#pragma unroll
        for (int mi = 0; mi < 2; mi++)
#pragma unroll
            for (int ni = 0; ni < 2; ni++) {
                int rowl = wm*32 + mi*16 + rl;
                int coll = wn*16 + ni*8 + cl;
                accs[mi][ni][0] *= scale; accs[mi][ni][1] *= scale;
                accs[mi][ni][2] *= scale; accs[mi][ni][3] *= scale;
                if (ch == rb) {
                    if (coll     > rowl) accs[mi][ni][0] = -1e9f;
                    if (coll + 1 > rowl) accs[mi][ni][1] = -1e9f;
                    if (coll     > rowl + 8) accs[mi][ni][2] = -1e9f;
                    if (coll + 1 > rowl + 8) accs[mi][ni][3] = -1e9f;
                }
            }
#pragma unroll
        for (int mi = 0; mi < 2; mi++) {
            float mx0 = fmaxf(fmaxf(accs[mi][0][0], accs[mi][0][1]),
                              fmaxf(accs[mi][1][0], accs[mi][1][1]));
            float mx1 = fmaxf(fmaxf(accs[mi][0][2], accs[mi][0][3]),
                              fmaxf(accs[mi][1][2], accs[mi][1][3]));
            mx0 = fmaxf(mx0, __shfl_xor_sync(0xffffffffu, mx0, 1));
            mx0 = fmaxf(mx0, __shfl_xor_sync(0xffffffffu, mx0, 2));
            mx1 = fmaxf(mx1, __shfl_xor_sync(0xffffffffu, mx1, 1));
            mx1 = fmaxf(mx1, __shfl_xor_sync(0xffffffffu, mx1, 2));
            if ((lane & 3) == 0) {
                wmax[wm*32 + mi*16 + rl][wn]     = mx0;
                wmax[wm*32 + mi*16 + rl + 8][wn] = mx1;
            }
        }
        __syncthreads();
        if (tid < 64) {
            float mc = fmaxf(fmaxf(wmax[tid][0], wmax[tid][1]),
                             fmaxf(wmax[tid][2], wmax[tid][3]));
            float mo = m_s[tid];
            float mn = fmaxf(mo, mc);
            alpha_s[tid] = __expf(mo - mn);
            m_s[tid] = mn;
        }
        __syncthreads();
#pragma unroll
        for (int mi = 0; mi < 2; mi++) {
            int rr0 = wm*32 + mi*16 + rl, rr1 = rr0 + 8;
            float mr0 = m_s[rr0], mr1 = m_s[rr1];
            float s0 = 0.0f, s1 = 0.0f;
#pragma unroll
            for (int ni = 0; ni < 2; ni++) {
                int coll = wn*16 + ni*8 + cl;
                float p00 = __expf(accs[mi][ni][0] - mr0);
                float p01 = __expf(accs[mi][ni][1] - mr0);
                float p10 = __expf(accs[mi][ni][2] - mr1);
                float p11 = __expf(accs[mi][ni][3] - mr1);
                s0 += p00 + p01; s1 += p10 + p11;
                __half2 h0, h1;
                h0.x = __float2half_rn(p00); h0.y = __float2half_rn(p01);
                h1.x = __float2half_rn(p10); h1.y = __float2half_rn(p11);
                *(__half2*)(sma + LP + aswz(rr0, coll >> 3) + (coll & 7) * 2) = h0;
                *(__half2*)(sma + LP + aswz(rr1, coll >> 3) + (coll & 7) * 2) = h1;
            }
            s0 += __shfl_xor_sync(0xffffffffu, s0, 1);
            s0 += __shfl_xor_sync(0xffffffffu, s0, 2);
            s1 += __shfl_xor_sync(0xffffffffu, s1, 1);
            s1 += __shfl_xor_sync(0xffffffffu, s1, 2);
            if ((lane & 3) == 0) { wsum[rr0][wn] = s0; wsum[rr1][wn] = s1; }
            float a0 = alpha_s[rr0], a1 = alpha_s[rr1];
#pragma unroll
            for (int ni = 0; ni < 4; ni++) {
                accd[mi][ni][0] *= a0; accd[mi][ni][1] *= a0;
                accd[mi][ni][2] *= a1; accd[mi][ni][3] *= a1;
            }
        }
        __syncthreads();
        if (tid < 64)
            l_s[tid] = alpha_s[tid] * l_s[tid]
                     + wsum[tid][0] + wsum[tid][1] + wsum[tid][2] + wsum[tid][3];
#pragma unroll
        for (int ks = 0; ks < 4; ks++) {
            uint32_t pa[2][4];
#pragma unroll
            for (int mi = 0; mi < 2; mi++) {
                int arow = wm*32 + mi*16 + (lane & 7) + ((lane >> 3) & 1) * 8;
                int pch  = ks*2 + ((lane >> 4) & 1);
                ldsm4(s_p + aswz(arow, pch), pa[mi]);
            }
#pragma unroll
            for (int ntp = 0; ntp < 2; ntp++) {
                int vrow = ks*16 + (lane & 7) + ((lane >> 3) & 1) * 8;
                int vch  = wn*4 + ntp*2 + ((lane >> 4) & 1);
                uint32_t t4[4];
                ldsm4t(vb + swzh(vrow, vch), t4);
                uint32_t b0[2] = {t4[0], t4[1]}, b1[2] = {t4[2], t4[3]};
#pragma unroll
                for (int mi = 0; mi < 2; mi++) {
                    mma16816(accd[mi][ntp*2],     pa[mi], b0);
                    mma16816(accd[mi][ntp*2 + 1], pa[mi], b1);
                }
            }
        }
        __syncthreads();
        if (ch + 2 <= rb) load_kv(ch + 2);
        CP_COMMIT();
    }

#pragma unroll
    for (int mi = 0; mi < 2; mi++)
#pragma unroll
        for (int ni = 0; ni < 4; ni++) {
            int rowl0 = wm*32 + mi*16 + rl;
            int col   = wn*32 + ni*8 + cl;
#pragma unroll
            for (int rr2 = 0; rr2 < 2; rr2++) {
                int rowl = rowl0 + rr2*8;
                float invl = 1.0f / l_s[rowl];
                __half2 o;
                o.x = __float2half_rn(accd[mi][ni][rr2*2]   * invl);
                o.y = __float2half_rn(accd[mi][ni][rr2*2+1] * invl);
                *(__half2*)(dot + (rowbase + r0 + rowl) * Dd + colbase + col) = o;
            }
        }
}

// ----- state path: recurrence, fp32 master in gmem, mem16 in smem -----
__device__ void attn_state_body(const __half* __restrict__ sq, const __half* __restrict__ sk,
                                const __half* __restrict__ v, __half* __restrict__ memo,
                                char* sms, int slice)
{
    const uint32_t s_base = smem_u32(sms);
    __shared__ float z_s[128], den_s[64], denk_s[64];

    const int tid = threadIdx.x;
    const int lane = tid & 31;
    const int w = tid >> 5;
    const int wm = w >> 1;
    const int wn = w & 1;
    const int bh = slice >> 1;
    const int half = slice & 1;
    const int dvb = half * 64;
    const int b = bh >> 4, h = bh & 15;
    const int colbase = h * 128;
    const int rl = lane >> 2, cl = (lane & 3) * 2;

    for (int i = tid; i < 4096; i += 256) ((uint32_t*)sms)[i] = 0u;
    if (tid < 128) z_s[tid] = 1.0f / 128.0f;

    auto prefetch = [&](int idx, int buf) {
        const int seg = idx >> 3, rb = idx & 7;
        const size_t rowb = (size_t)(b * Ss + seg * Ll) + rb * 64;
        const uint32_t Bo = s_base + SBUF + buf * SBUFSZ;
#pragma unroll
        for (int t = 0; t < 4; t++) {
            int i2 = tid + t * 256, row = i2 >> 4, c = i2 & 15;
            size_t g = (rowb + row) * Dd + colbase + c * 8;
            cp_async16(Bo + SOFF_SQ + swzh(row, c), sq + g);
            cp_async16(Bo + SOFF_SK + swzh(row, c), sk + g);
        }
#pragma unroll
        for (int t = 0; t < 2; t++) {
            int i2 = tid + t * 256, row = i2 >> 3, c = i2 & 7;
            size_t g = (rowb + row) * Dd + colbase + dvb + c * 8;
            cp_async16(Bo + SOFF_V + aswz(row, c), v + g);
        }
    };

    __syncthreads();
    prefetch(0, 0); CP_COMMIT();
    prefetch(1, 1); CP_COMMIT();

    float upd[2][4][4];
#pragma unroll
    for (int a2 = 0; a2 < 2; a2++)
#pragma unroll
        for (int b2 = 0; b2 < 4; b2++)
#pragma unroll
            for (int c2 = 0; c2 < 4; c2++) upd[a2][b2][c2] = 0.0f;
    float zacc = 0.0f;

    for (int idx = 0; idx < 64; idx++) {
        const int buf = idx & 1;
        const int seg = idx >> 3, rb = idx & 7;
        const size_t rowb = (size_t)(b * Ss + seg * Ll) + rb * 64;
        const uint32_t Bo = s_base + SBUF + buf * SBUFSZ;
        char* Bc = sms + SBUF + buf * SBUFSZ;

        CP_WAIT1();
        __syncthreads();

        {
            int row = tid >> 2, qtr = tid & 3;
            float ds = 0.0f, dk2 = 0.0f;
#pragma unroll
            for (int pi = 0; pi < 16; pi++) {
                int p = qtr * 16 + pi;
                uint32_t off = swzh(row, p >> 2) + (p & 3) * 4;
                __half2 hq = *(__half2*)(Bc + SOFF_SQ + off);
                __half2 hk = *(__half2*)(Bc + SOFF_SK + off);
                float z0 = z_s[2*p], z1 = z_s[2*p + 1];
                ds  += __half2float(hq.x) * z0 + __half2float(hq.y) * z1;
                dk2 += __half2float(hk.x) * z0 + __half2float(hk.y) * z1;
            }
            ds  += __shfl_xor_sync(0xffffffffu, ds, 1);
            ds  += __shfl_xor_sync(0xffffffffu, ds, 2);
            dk2 += __shfl_xor_sync(0xffffffffu, dk2, 1);
            dk2 += __shfl_xor_sync(0xffffffffu, dk2, 2);
            if (qtr == 0) { den_s[row] = ds; denk_s[row] = dk2; }
        }

        float accm[4][4], accv[4][4];
#pragma unroll
        for (int i = 0; i < 4; i++)
#pragma unroll
            for (int j = 0; j < 4; j++) { accm[i][j] = 0.0f; accv[i][j] = 0.0f; }
#pragma unroll
        for (int ks = 0; ks < 8; ks++) {
            uint32_t aq[4], ak[4];
            int arow = wm*16 + (lane & 7) + ((lane >> 3) & 1) * 8;
            int ach  = ks*2 + ((lane >> 4) & 1);
            ldsm4(Bo + SOFF_SQ + swzh(arow, ach), aq);
            ldsm4(Bo + SOFF_SK + swzh(arow, ach), ak);
#pragma unroll
            for (int ntp = 0; ntp < 2; ntp++) {
                int mrow = ks*16 + (lane & 7) + ((lane >> 3) & 1) * 8;
                int mch  = wn*4 + ntp*2 + ((lane >> 4) & 1);
                uint32_t t4[4];
                ldsm4t(s_base + aswz(mrow, mch), t4);
                uint32_t b0[2] = {t4[0], t4[1]}, b1[2] = {t4[2], t4[3]};
                mma16816(accm[ntp*2],     aq, b0);
                mma16816(accm[ntp*2 + 1], aq, b1);
                mma16816(accv[ntp*2],     ak, b0);
                mma16816(accv[ntp*2 + 1], ak, b1);
            }
        }
        __syncthreads();

#pragma unroll
        for (int ni = 0; ni < 4; ni++) {
            int col = wn*32 + ni*8 + cl;
#pragma unroll
            for (int rr2 = 0; rr2 < 2; rr2++) {
                int rowl = wm*16 + rl + rr2*8;
                float invd = 1.0f / den_s[rowl];
                float invk = 1.0f / denk_s[rowl];
                uint32_t soff = aswz(rowl, col >> 3) + (col & 7) * 2;
                __half2 vv = *(__half2*)(Bc + SOFF_V + soff);
                __half2 o, od;
                o.x = __float2half_rn(accm[ni][rr2*2]   * invd);
                o.y = __float2half_rn(accm[ni][rr2*2+1] * invd);
                od.x = __float2half_rn(__half2float(vv.x) - accv[ni][rr2*2]   * invk);
                od.y = __float2half_rn(__half2float(vv.y) - accv[ni][rr2*2+1] * invk);
                *(__half2*)(memo + (rowb + rowl) * Dd + colbase + dvb + col) = o;
                *(__half2*)(Bc + SOFF_V + soff) = od;
            }
        }
        __syncthreads();

#pragma unroll
        for (int ks = 0; ks < 4; ks++) {
            uint32_t a2[2][4];
#pragma unroll
            for (int mt = 0; mt < 2; mt++) {
                int srow = ks*16 + (lane & 7) + ((lane >> 4) & 1) * 8;
                int sch  = wm*4 + mt*2 + ((lane >> 3) & 1);
                ldsm4t(Bo + SOFF_SK + swzh(srow, sch), a2[mt]);
            }
#pragma unroll
            for (int ntp = 0; ntp < 2; ntp++) {
                int vrow = ks*16 + (lane & 7) + ((lane >> 3) & 1) * 8;
                int vch  = wn*4 + ntp*2 + ((lane >> 4) & 1);
                uint32_t t4[4];
                ldsm4t(Bo + SOFF_V + aswz(vrow, vch), t4);
                uint32_t b0[2] = {t4[0], t4[1]}, b1[2] = {t4[2], t4[3]};
#pragma unroll
                for (int mt = 0; mt < 2; mt++) {
                    mma16816(upd[mt][ntp*2],     a2[mt], b0);
                    mma16816(upd[mt][ntp*2 + 1], a2[mt], b1);
                }
            }
        }
        if (tid < 128) {
#pragma unroll 8
            for (int r = 0; r < 64; r++) {
                __half hv = *(__half*)(Bc + SOFF_SK + swzh(r, tid >> 3) + (tid & 7) * 2);
                zacc += __half2float(hv);
            }
        }

        if (rb == 7) {
#pragma unroll
            for (int mt = 0; mt < 2; mt++)
#pragma unroll
                for (int ni = 0; ni < 4; ni++) {
                    int dv = wn*32 + ni*8 + cl;
#pragma unroll
                    for (int rr2 = 0; rr2 < 2; rr2++) {
                        int dk = wm*32 + mt*16 + rl + rr2*8;
                        float2* pf = (float2*)&g_mem32[(size_t)slice * 8192 + dk * 64 + dv];
                        float2 cur;
                        if (seg == 0) {
                            cur.x = upd[mt][ni][rr2*2];
                            cur.y = upd[mt][ni][rr2*2+1];
                        } else {
                            cur = *pf;
                            cur.x += upd[mt][ni][rr2*2];
                            cur.y += upd[mt][ni][rr2*2+1];
                        }
                        *pf = cur;
                        __half2 hm;
                        hm.x = __float2half_rn(cur.x);
                        hm.y = __float2half_rn(cur.y);
                        *(__half2*)(sms + aswz(dk, dv >> 3) + (dv & 7) * 2) = hm;
                        upd[mt][ni][rr2*2] = 0.0f;
                        upd[mt][ni][rr2*2+1] = 0.0f;
                    }
                }
            if (tid < 128) { z_s[tid] += zacc; zacc = 0.0f; }
        }
        __syncthreads();
        if (idx + 2 < 64) prefetch(idx + 2, buf);
        CP_COMMIT();
    }
}

__global__ void __launch_bounds__(256, 2)
attn_fused(const __half* __restrict__ q, const __half* __restrict__ k,
           const __half* __restrict__ v, const __half* __restrict__ sq,
           const __half* __restrict__ sk,
           __half* __restrict__ dot, __half* __restrict__ memo)
{
    extern __shared__ char sma[];
    if (blockIdx.x < 64) {
        attn_state_body(sq, sk, v, memo, sma, blockIdx.x);
    } else {
        int lid = blockIdx.x - 64;
        attn_local_flash(q, k, v, dot, sma, lid & 7, (lid >> 3) & 7, lid >> 6);
    }
}

// ---------------- combine: att = gate*memo + (1-gate)*dot ----------------
__global__ void __launch_bounds__(256)
combine_att(__half* __restrict__ att, const __half* __restrict__ dot,
            const float* __restrict__ betas)
{
    size_t i8 = (size_t)blockIdx.x * 256 + threadIdx.x;
    size_t e0 = i8 * 8;
    int c0 = (int)(e0 & 2047);
    uint4 mu = *(uint4*)(att + e0);
    uint4 du = *(const uint4*)(dot + e0);
    __half* mh = (__half*)&mu;
    __half* dh = (__half*)&du;
    __half out[8];
#pragma unroll
    for (int j = 0; j < 8; j++) {
        float g = 1.0f / (1.0f + __expf(-betas[c0 + j]));
        out[j] = __float2half_rn(g * __half2float(mh[j]) + (1.0f - g) * __half2float(dh[j]));
    }
    *(uint4*)(att + e0) = *(uint4*)out;
}

// ---------------- residual + LayerNorm (float4) ----------------
__global__ void __launch_bounds__(256)
resid_ln(const float* __restrict__ h2, const float* __restrict__ x,
         const float* __restrict__ w, const float* __restrict__ bsh,
         float* __restrict__ out)
{
    __shared__ float ybuf[Dd];
    __shared__ float red[17];
    const int row = blockIdx.x;
    const int tid = threadIdx.x;
    const float4* hr = (const float4*)(h2 + (size_t)row * Dd);
    const float4* xr = (const float4*)(x  + (size_t)row * Dd);

    float s = 0.0f, sq = 0.0f;
#pragma unroll
    for (int t = 0; t < 2; t++) {
        int c4 = tid + t * 256;
        float4 hv = hr[c4], xv = xr[c4];
        float4 yv;
        yv.x = hv.x + xv.x; yv.y = hv.y + xv.y;
        yv.z = hv.z + xv.z; yv.w = hv.w + xv.w;
        *(float4*)&ybuf[c4 * 4] = yv;
        s  += yv.x + yv.y + yv.z + yv.w;
        sq += yv.x*yv.x + yv.y*yv.y + yv.z*yv.z + yv.w*yv.w;
    }
#pragma unroll
    for (int o = 16; o > 0; o >>= 1) {
        s  += __shfl_xor_sync(0xffffffffu, s, o);
        sq += __shfl_xor_sync(0xffffffffu, sq, o);
    }
    int warp = tid >> 5, lane = tid & 31;
    if (lane == 0) { red[warp] = s; red[8 + warp] = sq; }
    __syncthreads();
    if (tid == 0) {
        float S = 0, SQ = 0;
        for (int i = 0; i < 8; i++) { S += red[i]; SQ += red[8 + i]; }
        red[0] = S; red[1] = SQ;
    }
    __syncthreads();
    float mu  = red[0] / (float)Dd;
    float var = red[1] / (float)Dd - mu * mu;
    float inv = rsqrtf(var + 1e-5f);
#pragma unroll
    for (int t = 0; t < 2; t++) {
        int c4 = tid + t * 256;
        float4 yv = *(float4*)&ybuf[c4 * 4];
        float4 wv = *(const float4*)(w + c4 * 4);
        float4 bv = *(const float4*)(bsh + c4 * 4);
        float4 o;
        o.x = (yv.x - mu) * inv * wv.x + bv.x;
        o.y = (yv.y - mu) * inv * wv.y + bv.y;
        o.z = (yv.z - mu) * inv * wv.z + bv.z;
        o.w = (yv.w - mu) * inv * wv.w + bv.w;
        *(float4*)(out + (size_t)row * Dd + c4 * 4) = o;
    }
}

// ---------------- launch ----------------
extern "C" void kernel_launch(void* const* d_in, const int* in_sizes, int n_in,
                              void* d_out, int out_size)
{
    const float* x    = (const float*)d_in[0];
    const float* Wq   = (const float*)d_in[1];
    const float* bq   = (const float*)d_in[2];
    const float* Wk   = (const float*)d_in[3];
    const float* bk   = (const float*)d_in[4];
    const float* Wv   = (const float*)d_in[5];
    const float* bv   = (const float*)d_in[6];
    const float* Wo   = (const float*)d_in[7];
    const float* bo   = (const float*)d_in[8];
    const float* beta = (const float*)d_in[9];
    const float* W1   = (const float*)d_in[10];
    const float* b1   = (const float*)d_in[11];
    const float* W2   = (const float*)d_in[12];
    const float* b2   = (const float*)d_in[13];
    const float* lnw  = (const float*)d_in[14];
    const float* lnb  = (const float*)d_in[15];
    float* out = (float*)d_out;

    float *ph2;
    __half *pxh, *pqh, *pkh, *pvh, *psq, *psk, *pdot, *path, *pah, *ph1h;
    __half *wqkv, *wo, *w1, *w2;
    cudaGetSymbolAddress((void**)&ph2,  g_h2);
    cudaGetSymbolAddress((void**)&pxh,  g_x_h);
    cudaGetSymbolAddress((void**)&pqh,  g_q_h);
    cudaGetSymbolAddress((void**)&pkh,  g_k_h);
    cudaGetSymbolAddress((void**)&pvh,  g_v_h);
    cudaGetSymbolAddress((void**)&psq,  g_sq_h);
    cudaGetSymbolAddress((void**)&psk,  g_sk_h);
    cudaGetSymbolAddress((void**)&pdot, g_dot_h);
    cudaGetSymbolAddress((void**)&path, g_att_h);
    cudaGetSymbolAddress((void**)&pah,  g_a_h);
    cudaGetSymbolAddress((void**)&ph1h, g_h1_h);
    cudaGetSymbolAddress((void**)&wqkv, g_wqkv);
    cudaGetSymbolAddress((void**)&wo, g_wo);
    cudaGetSymbolAddress((void**)&w1, g_w1);
    cudaGetSymbolAddress((void**)&w2, g_w2);

    cudaFuncSetAttribute(attn_fused, cudaFuncAttributeMaxDynamicSharedMemorySize, FU_SMEM);
    cudaFuncSetAttribute(gemm_mma<0>, cudaFuncAttributeMaxDynamicSharedMemorySize, GEMM_SMEM_BYTES);
    cudaFuncSetAttribute(gemm_mma<1>, cudaFuncAttributeMaxDynamicSharedMemorySize, GEMM_SMEM_BYTES);
    cudaFuncSetAttribute(gemm_mma<2>, cudaFuncAttributeMaxDynamicSharedMemorySize, GEMM_SMEM_BYTES);
    cudaFuncSetAttribute(gemm_qkv,    cudaFuncAttributeMaxDynamicSharedMemorySize, GEMM_SMEM_BYTES);

    convt_all<<<16384, 256>>>(x, pxh, Wq, Wk, Wv, Wo, W1, W2,               // 1
                              wqkv, wo, w1, w2);
    gemm_qkv<<<dim3(48, 32), 256, GEMM_SMEM_BYTES>>>(                       // 2
        pxh, wqkv, bq, bk, bv, pqh, pkh, pvh, psq, psk, BSr, Dd);

    attn_fused<<<2112, 256, FU_SMEM>>>(pqh, pkh, pvh, psq, psk,             // 3
                                       pdot, path);
    combine_att<<<(BSr * Dd) / 2048, 256>>>(path, pdot, beta);              // 4

    dim3 gP(Dd/128, BSr/256);   // (16, 32)
    gemm_mma<1><<<gP, 256, GEMM_SMEM_BYTES>>>(path, wo, bo, nullptr, pah, BSr, Dd, Dd);   // 5
    dim3 gW1(DH/128, BSr/256);  // (64, 32)
    gemm_mma<2><<<gW1, 256, GEMM_SMEM_BYTES>>>(pah, w1, b1, nullptr, ph1h, BSr, DH, Dd);  // 6
    gemm_mma<0><<<gP, 256, GEMM_SMEM_BYTES>>>(ph1h, w2, b2, ph2, nullptr, BSr, Dd, DH);   // 7

    resid_ln<<<BSr, 256>>>(ph2, x, lnw, lnb, out);                          // 8
}

// round 13
// speedup vs baseline: 1.1427x; 1.1427x over previous
#include <cuda_runtime.h>
#include <cuda_fp16.h>
#include <cstdint>

// ---------------- problem constants ----------------
#define Bb   2
#define Ss   4096
#define Dd   2048
#define Hh   16
#define DH   8192
#define Ll   512
#define NSEGc 8
#define BSr  (Bb*Ss)
#define BHn  (Bb*Hh)

// ---------------- scratch ----------------
__device__ float g_h2 [(size_t)BSr*Dd];
__device__ __half g_x_h  [(size_t)BSr*Dd];
__device__ __half g_q_h  [(size_t)BSr*Dd];
__device__ __half g_k_h  [(size_t)BSr*Dd];
__device__ __half g_v_h  [(size_t)BSr*Dd];
__device__ __half g_sq_h [(size_t)BSr*Dd];
__device__ __half g_sk_h [(size_t)BSr*Dd];
__device__ __half g_dot_h[(size_t)BSr*Dd];
__device__ __half g_att_h[(size_t)BSr*Dd];
__device__ __half g_a_h  [(size_t)BSr*Dd];
__device__ __half g_h1_h [(size_t)BSr*DH];
// fp16 weights in NATIVE [K,N] layout (no transpose)
__device__ __half g_wq[(size_t)Dd*Dd];
__device__ __half g_wk[(size_t)Dd*Dd];
__device__ __half g_wv[(size_t)Dd*Dd];
__device__ __half g_wo[(size_t)Dd*Dd];
__device__ __half g_w1[(size_t)Dd*DH];
__device__ __half g_w2[(size_t)DH*Dd];
__device__ float  g_mem32[64 * 8192];

// ---------------- helpers ----------------
__device__ __forceinline__ float gelu_exact(float x) {
    return 0.5f * x * (1.0f + erff(x * 0.70710678118654752440f));
}
__device__ __forceinline__ float elu1(float x) {
    return (x > 0.0f) ? (x + 1.0f) : __expf(x);
}
__device__ __forceinline__ uint32_t smem_u32(const void* p) {
    uint32_t a;
    asm("{ .reg .u64 t; cvta.to.shared.u64 t, %1; cvt.u32.u64 %0, t; }" : "=r"(a) : "l"(p));
    return a;
}
__device__ __forceinline__ void mma16816(float* c, const uint32_t* a, const uint32_t* b) {
    asm volatile(
        "mma.sync.aligned.m16n8k16.row.col.f32.f16.f16.f32 "
        "{%0,%1,%2,%3}, {%4,%5,%6,%7}, {%8,%9}, {%0,%1,%2,%3};"
        : "+f"(c[0]), "+f"(c[1]), "+f"(c[2]), "+f"(c[3])
        : "r"(a[0]), "r"(a[1]), "r"(a[2]), "r"(a[3]), "r"(b[0]), "r"(b[1]));
}
__device__ __forceinline__ void ldsm4(uint32_t addr, uint32_t* r) {
    asm volatile("ldmatrix.sync.aligned.m8n8.x4.shared.b16 {%0,%1,%2,%3}, [%4];"
                 : "=r"(r[0]), "=r"(r[1]), "=r"(r[2]), "=r"(r[3]) : "r"(addr));
}
__device__ __forceinline__ void ldsm4t(uint32_t addr, uint32_t* r) {
    asm volatile("ldmatrix.sync.aligned.m8n8.x4.trans.shared.b16 {%0,%1,%2,%3}, [%4];"
                 : "=r"(r[0]), "=r"(r[1]), "=r"(r[2]), "=r"(r[3]) : "r"(addr));
}
__device__ __forceinline__ void cp_async16(uint32_t saddr, const void* gaddr) {
    asm volatile("cp.async.cg.shared.global [%0], [%1], 16;" :: "r"(saddr), "l"(gaddr));
}
#define CP_COMMIT() asm volatile("cp.async.commit_group;" ::: "memory")
#define CP_WAIT1()  asm volatile("cp.async.wait_group 1;" ::: "memory")
#define CP_WAIT0()  asm volatile("cp.async.wait_group 0;" ::: "memory")

__device__ __forceinline__ uint32_t aswz(int row, int chunk) {
    return (uint32_t)(row * 128 + ((chunk ^ (row & 7)) << 4));
}
__device__ __forceinline__ uint32_t swzh(int row, int chunk16) {
    return (uint32_t)(row * 256 + ((chunk16 ^ (row & 7)) << 4));
}

// ---------------- pure fp32 -> fp16 convert (x + all weights, flat) ----------------
// block = 8192 elems (256 threads x 8 float4)
__global__ void __launch_bounds__(256)
conv_all(const float* __restrict__ x, __half* __restrict__ xh,
         const float* __restrict__ Wq, const float* __restrict__ Wk,
         const float* __restrict__ Wv, const float* __restrict__ Wo,
         const float* __restrict__ W1, const float* __restrict__ W2,
         __half* twq, __half* twk, __half* twv, __half* two_,
         __half* tw1, __half* tw2)
{
    const int id = blockIdx.x;
    const int tid = threadIdx.x;
    const float* src; __half* dst; size_t base;
    if (id < 2048)      { src = x;  dst = xh;  base = (size_t)id * 8192; }
    else if (id < 2560) { src = Wq; dst = twq; base = (size_t)(id - 2048) * 8192; }
    else if (id < 3072) { src = Wk; dst = twk; base = (size_t)(id - 2560) * 8192; }
    else if (id < 3584) { src = Wv; dst = twv; base = (size_t)(id - 3072) * 8192; }
    else if (id < 4096) { src = Wo; dst = two_; base = (size_t)(id - 3584) * 8192; }
    else if (id < 6144) { src = W1; dst = tw1; base = (size_t)(id - 4096) * 8192; }
    else                { src = W2; dst = tw2; base = (size_t)(id - 6144) * 8192; }
#pragma unroll
    for (int t = 0; t < 2; t++) {
        size_t e = base + (tid + t * 256) * 16;       // 16 elems per thread-iter
        float4 v0 = *(const float4*)(src + e);
        float4 v1 = *(const float4*)(src + e + 4);
        float4 v2 = *(const float4*)(src + e + 8);
        float4 v3 = *(const float4*)(src + e + 12);
        __half h[16];
        h[0]=__float2half_rn(v0.x); h[1]=__float2half_rn(v0.y);
        h[2]=__float2half_rn(v0.z); h[3]=__float2half_rn(v0.w);
        h[4]=__float2half_rn(v1.x); h[5]=__float2half_rn(v1.y);
        h[6]=__float2half_rn(v1.z); h[7]=__float2half_rn(v1.w);
        h[8]=__float2half_rn(v2.x); h[9]=__float2half_rn(v2.y);
        h[10]=__float2half_rn(v2.z); h[11]=__float2half_rn(v2.w);
        h[12]=__float2half_rn(v3.x); h[13]=__float2half_rn(v3.y);
        h[14]=__float2half_rn(v3.z); h[15]=__float2half_rn(v3.w);
        *(uint4*)(dst + e)     = *(uint4*)h;
        *(uint4*)(dst + e + 8) = *(uint4*)(h + 8);
    }
}

// ---------------- GEMM core: 128x128 CTA, warp 32x64, BK=64, 3-stage ----------------
// A: [M,K] row-major (aswz tiles, ldsm4). B: [K,N] row-major (swzh tiles, ldsm4t).
#define GEMM_STAGE_BYTES 32768            // A 16KB + B 16KB
#define GEMM_SMEM_BYTES  (3 * GEMM_STAGE_BYTES)

template<typename EpiF>
__device__ __forceinline__ void gemm_body(
    const __half* __restrict__ A, const __half* __restrict__ Bp,
    int M, int N, int K, int Nw, int bnw, uint32_t smem, EpiF epi)
{
    const int tid  = threadIdx.x;
    const int lane = tid & 31;
    const int w    = tid >> 5;
    const int wm   = w & 3;
    const int wn   = w >> 2;
    const size_t bm = (size_t)blockIdx.y * 128;
    const int KT = K >> 6;

    const int a_row = wm * 32 + (lane & 7) + ((lane >> 3) & 1) * 8;
    const int a_ch  = (lane >> 4) & 1;
    const int b_krow = (lane & 7) + ((lane >> 3) & 1) * 8;
    const int b_chb  = wn * 8 + ((lane >> 4) & 1);

    const int rrA = tid >> 3, ccA = tid & 7;     // A: 32 rows x 8 chunks per pass
    const int rrB = tid >> 4, ccB = tid & 15;    // B: 16 rows x 16 chunks per pass

    float acc[2][8][4];
#pragma unroll
    for (int i = 0; i < 2; i++)
#pragma unroll
        for (int j = 0; j < 8; j++)
#pragma unroll
            for (int q = 0; q < 4; q++) acc[i][j][q] = 0.0f;

    auto load_stage = [&](int st, int itk) {
        const uint32_t sa = smem + st * GEMM_STAGE_BYTES;
        const uint32_t sb = sa + 16384;
        const size_t k0 = (size_t)itk * 64;
#pragma unroll
        for (int t = 0; t < 4; t++) {
            int row = rrA + t * 32;
            cp_async16(sa + aswz(row, ccA), A + (bm + row) * (size_t)K + k0 + ccA * 8);
        }
#pragma unroll
        for (int t = 0; t < 4; t++) {
            int row = rrB + t * 16;
            cp_async16(sb + swzh(row, ccB), Bp + (k0 + row) * (size_t)Nw + bnw + ccB * 8);
        }
    };

    load_stage(0, 0); CP_COMMIT();
    load_stage(1, 1); CP_COMMIT();

    int cur = 0;
    for (int it = 0; it < KT; it++) {
        CP_WAIT1();
        __syncthreads();
        int nxt = cur + 2; if (nxt >= 3) nxt -= 3;
        if (it + 2 < KT) load_stage(nxt, it + 2);
        CP_COMMIT();

        const uint32_t sa = smem + cur * GEMM_STAGE_BYTES;
        const uint32_t sb = sa + 16384;
#pragma unroll
        for (int ks = 0; ks < 4; ks++) {
            uint32_t ah[2][4];
#pragma unroll
            for (int mi = 0; mi < 2; mi++)
                ldsm4(sa + aswz(a_row + mi * 16, ks * 2 + a_ch), ah[mi]);
            uint32_t bh[8][2];
#pragma unroll
            for (int nt = 0; nt < 4; nt++) {
                uint32_t t4[4];
                ldsm4t(sb + swzh(ks * 16 + b_krow, b_chb + nt * 2), t4);
                bh[2*nt][0] = t4[0]; bh[2*nt][1] = t4[1];
                bh[2*nt+1][0] = t4[2]; bh[2*nt+1][1] = t4[3];
            }
#pragma unroll
            for (int mi = 0; mi < 2; mi++)
#pragma unroll
                for (int ni = 0; ni < 8; ni++)
                    mma16816(acc[mi][ni], ah[mi], bh[ni]);
        }
        cur = cur + 1; if (cur >= 3) cur -= 3;
    }

    const int rl = lane >> 2, cl = (lane & 3) * 2;
#pragma unroll
    for (int mi = 0; mi < 2; mi++)
#pragma unroll
        for (int ni = 0; ni < 8; ni++) {
            size_t row0 = bm + wm * 32 + mi * 16 + rl;
            size_t col  = (size_t)blockIdx.x * 128 + wn * 64 + ni * 8 + cl;
            epi(acc[mi][ni], row0, col);
        }
}

template<int EPI>
__global__ void __launch_bounds__(256, 2)
gemm_mma(const __half* __restrict__ A, const __half* __restrict__ Bp,
         const float* __restrict__ bias,
         float* __restrict__ Cf, __half* __restrict__ Ch, int M, int N, int K)
{
    extern __shared__ char sm_raw[];
    gemm_body(A, Bp, M, N, K, N, (int)(blockIdx.x * 128), smem_u32(sm_raw),
        [&](const float* c, size_t row0, size_t col) {
            const float b0 = bias[col], b1 = bias[col + 1];
            float v00 = c[0] + b0, v01 = c[1] + b1;
            float v10 = c[2] + b0, v11 = c[3] + b1;
            if (EPI == 2) {
                v00 = gelu_exact(v00); v01 = gelu_exact(v01);
                v10 = gelu_exact(v10); v11 = gelu_exact(v11);
            }
            if (EPI == 0) {
                *(float2*)(Cf + row0 * (size_t)N + col)       = make_float2(v00, v01);
                *(float2*)(Cf + (row0 + 8) * (size_t)N + col) = make_float2(v10, v11);
            } else {
                __half2 p0, p1;
                p0.x = __float2half_rn(v00); p0.y = __float2half_rn(v01);
                p1.x = __float2half_rn(v10); p1.y = __float2half_rn(v11);
                *(__half2*)(Ch + row0 * (size_t)N + col)       = p0;
                *(__half2*)(Ch + (row0 + 8) * (size_t)N + col) = p1;
            }
        });
}

// fused QKV GEMM: blockIdx.x in [0,48) -> sel = x>>4, local N block = x&15
__global__ void __launch_bounds__(256, 2)
gemm_qkv(const __half* __restrict__ A,
         const __half* __restrict__ Bq, const __half* __restrict__ Bk,
         const __half* __restrict__ Bv,
         const float* __restrict__ bq, const float* __restrict__ bk,
         const float* __restrict__ bv,
         __half* __restrict__ qh, __half* __restrict__ kh, __half* __restrict__ vh,
         __half* __restrict__ sqh, __half* __restrict__ skh, int M, int K)
{
    extern __shared__ char sm_raw[];
    const int sel = (int)(blockIdx.x >> 4);
    const int nb  = (int)(blockIdx.x & 15);
    const __half* Bp = (sel == 0) ? Bq : (sel == 1) ? Bk : Bv;
    const float* bias = (sel == 0) ? bq : (sel == 1) ? bk : bv;
    __half* outp = (sel == 0) ? qh : (sel == 1) ? kh : vh;
    __half* sigp = (sel == 0) ? sqh : (sel == 1) ? skh : nullptr;

    gemm_body(A, Bp, M, Dd, K, Dd, nb * 128, smem_u32(sm_raw),
        [&](const float* c, size_t row0, size_t col) {
            size_t lc = (col - (size_t)blockIdx.x * 128) + (size_t)nb * 128;
            const float b0 = bias[lc], b1 = bias[lc + 1];
            float v00 = c[0] + b0, v01 = c[1] + b1;
            float v10 = c[2] + b0, v11 = c[3] + b1;
            __half2 p0, p1;
            p0.x = __float2half_rn(v00); p0.y = __float2half_rn(v01);
            p1.x = __float2half_rn(v10); p1.y = __float2half_rn(v11);
            *(__half2*)(outp + row0 * (size_t)Dd + lc)       = p0;
            *(__half2*)(outp + (row0 + 8) * (size_t)Dd + lc) = p1;
            if (sel < 2) {
                __half2 s0, s1;
                s0.x = __float2half_rn(elu1(v00)); s0.y = __float2half_rn(elu1(v01));
                s1.x = __float2half_rn(elu1(v10)); s1.y = __float2half_rn(elu1(v11));
                *(__half2*)(sigp + row0 * (size_t)Dd + lc)       = s0;
                *(__half2*)(sigp + (row0 + 8) * (size_t)Dd + lc) = s1;
            }
        });
}

// ---------------- fused attention (2 CTAs/SM) — unchanged from R11 ----------------
#define FU_SMEM 98304
#define LQ  0
#define LK0 16384
#define LK1 32768
#define LV0 49152
#define LV1 65536
#define LP  81920
#define SBUF   16384
#define SBUFSZ 40960
#define SOFF_SQ 0
#define SOFF_SK 16384
#define SOFF_V  32768

__device__ void attn_local_flash(const __half* __restrict__ q, const __half* __restrict__ k,
                                 const __half* __restrict__ v, __half* __restrict__ dot,
                                 char* sma, int rb, int seg, int bh)
{
    const uint32_t s_q = smem_u32(sma);
    const uint32_t s_k[2] = { s_q + LK0, s_q + LK1 };
    const uint32_t s_v[2] = { s_q + LV0, s_q + LV1 };
    const uint32_t s_p = s_q + LP;
    __shared__ float m_s[64], l_s[64], alpha_s[64], wmax[64][4], wsum[64][4];

    const int tid = threadIdx.x;
    const int lane = tid & 31;
    const int w = tid >> 5;
    const int wm = w >> 2;
    const int wn = w & 3;
    const int b = bh >> 4, h = bh & 15;
    const int r0 = rb * 64;
    const size_t rowbase = (size_t)(b * Ss + seg * Ll);
    const int colbase = h * 128;
    const int rl = lane >> 2, cl = (lane & 3) * 2;
    const float scale = 0.088388347648318447f;

    if (tid < 64) { m_s[tid] = -1e30f; l_s[tid] = 0.0f; }

    auto load_kv = [&](int ch) {
        const uint32_t kd = s_k[ch & 1], vd = s_v[ch & 1];
#pragma unroll
        for (int t = 0; t < 4; t++) {
            int idx = tid + t * 256, row = idx >> 4, c = idx & 15;
            size_t g = (rowbase + ch * 64 + row) * Dd + colbase + c * 8;
            cp_async16(kd + swzh(row, c), k + g);
            cp_async16(vd + swzh(row, c), v + g);
        }
    };

#pragma unroll
    for (int t = 0; t < 4; t++) {
        int idx = tid + t * 256, row = idx >> 4, c = idx & 15;
        cp_async16(s_q + swzh(row, c), q + (rowbase + r0 + row) * Dd + colbase + c * 8);
    }
    load_kv(0); CP_COMMIT();
    if (rb >= 1) load_kv(1);
    CP_COMMIT();

    float accd[2][4][4];
#pragma unroll
    for (int i = 0; i < 2; i++)
#pragma unroll
        for (int j = 0; j < 4; j++)
#pragma unroll
            for (int qq = 0; qq < 4; qq++) accd[i][j][qq] = 0.0f;

    for (int ch = 0; ch <= rb; ch++) {
        CP_WAIT1();
        __syncthreads();
        const uint32_t kb = s_k[ch & 1], vb = s_v[ch & 1];

        float accs[2][2][4];
#pragma unroll
        for (int i = 0; i < 2; i++)
#pragma unroll
            for (int j = 0; j < 2; j++)
#pragma unroll
                for (int qq = 0; qq < 4; qq++) accs[i][j][qq] = 0.0f;
#pragma unroll
        for (int ks = 0; ks < 8; ks++) {
            uint32_t a[2][4];
#pragma unroll
            for (int mi = 0; mi < 2; mi++) {
                int arow = wm*32 + mi*16 + (lane & 7) + ((lane >> 3) & 1) * 8;
                int ach  = ks*2 + ((lane >> 4) & 1);
                ldsm4(s_q + swzh(arow, ach), a[mi]);
            }
            uint32_t t4[4];
            int brow = wn*16 + (lane & 7) + ((lane >> 4) & 1) * 8;
            int bch  = ks*2 + ((lane >> 3) & 1);
            ldsm4(kb + swzh(brow, bch), t4);
            uint32_t b0[2] = {t4[0], t4[1]}, b1[2] = {t4[2], t4[3]};
#pragma unroll
            for (int mi = 0; mi < 2; mi++) {
                mma16816(accs[mi][0], a[mi], b0);
                mma16816(accs[mi][1], a[mi], b1);
            }
        }
#pragma unroll
        for (int mi = 0; mi < 2; mi++)
#pragma unroll
            for (int ni = 0; ni < 2; ni++) {
                int rowl = wm*32 + mi*16 + rl;
                int coll = wn*16 + ni*8 + cl;
                accs[mi][ni][0] *= scale; accs[mi][ni][1] *= scale;
                accs[mi][ni][2] *= scale; accs[mi][ni][3] *= scale;
                if (ch == rb) {
                    if (coll     > rowl) accs[mi][ni][0] = -1e9f;
                    if (coll + 1 > rowl) accs[mi][ni][1] = -1e9f;
                    if (coll     > rowl + 8) accs[mi][ni][2] = -1e9f;
                    if (coll + 1 > rowl + 8) accs[mi][ni][3] = -1e9f;
                }
            }
#pragma unroll
        for (int mi = 0; mi < 2; mi++) {
            float mx0 = fmaxf(fmaxf(accs[mi][0][0], accs[mi][0][1]),
                              fmaxf(accs[mi][1][0], accs[mi][1][1]));
            float mx1 = fmaxf(fmaxf(accs[mi][0][2], accs[mi][0][3]),
                              fmaxf(accs[mi][1][2], accs[mi][1][3]));
            mx0 = fmaxf(mx0, __shfl_xor_sync(0xffffffffu, mx0, 1));
            mx0 = fmaxf(mx0, __shfl_xor_sync(0xffffffffu, mx0, 2));
            mx1 = fmaxf(mx1, __shfl_xor_sync(0xffffffffu, mx1, 1));
            mx1 = fmaxf(mx1, __shfl_xor_sync(0xffffffffu, mx1, 2));
            if ((lane & 3) == 0) {
                wmax[wm*32 + mi*16 + rl][wn]     = mx0;
                wmax[wm*32 + mi*16 + rl + 8][wn] = mx1;
            }
        }
        __syncthreads();
        if (tid < 64) {
            float mc = fmaxf(fmaxf(wmax[tid][0], wmax[tid][1]),
                             fmaxf(wmax[tid][2], wmax[tid][3]));
            float mo = m_s[tid];
            float mn = fmaxf(mo, mc);
            alpha_s[tid] = __expf(mo - mn);
            m_s[tid] = mn;
        }
        __syncthreads();
#pragma unroll
        for (int mi = 0; mi < 2; mi++) {
            int rr0 = wm*32 + mi*16 + rl, rr1 = rr0 + 8;
            float mr0 = m_s[rr0], mr1 = m_s[rr1];
            float s0 = 0.0f, s1 = 0.0f;
#pragma unroll
            for (int ni = 0; ni < 2; ni++) {
                int coll = wn*16 + ni*8 + cl;
                float p00 = __expf(accs[mi][ni][0] - mr0);
                float p01 = __expf(accs[mi][ni][1] - mr0);
                float p10 = __expf(accs[mi][ni][2] - mr1);
                float p11 = __expf(accs[mi][ni][3] - mr1);
                s0 += p00 + p01; s1 += p10 + p11;
                __half2 h0, h1;
                h0.x = __float2half_rn(p00); h0.y = __float2half_rn(p01);
                h1.x = __float2half_rn(p10); h1.y = __float2half_rn(p11);
                *(__half2*)(sma + LP + aswz(rr0, coll >> 3) + (coll & 7) * 2) = h0;
                *(__half2*)(sma + LP + aswz(rr1, coll >> 3) + (coll & 7) * 2) = h1;
            }
            s0 += __shfl_xor_sync(0xffffffffu, s0, 1);
            s0 += __shfl_xor_sync(0xffffffffu, s0, 2);
            s1 += __shfl_xor_sync(0xffffffffu, s1, 1);
            s1 += __shfl_xor_sync(0xffffffffu, s1, 2);
            if ((lane & 3) == 0) { wsum[rr0][wn] = s0; wsum[rr1][wn] = s1; }
            float a0 = alpha_s[rr0], a1 = alpha_s[rr1];
#pragma unroll
            for (int ni = 0; ni < 4; ni++) {
                accd[mi][ni][0] *= a0; accd[mi][ni][1] *= a0;
                accd[mi][ni][2] *= a1; accd[mi][ni][3] *= a1;
            }
        }
        __syncthreads();
        if (tid < 64)
            l_s[tid] = alpha_s[tid] * l_s[tid]
                     + wsum[tid][0] + wsum[tid][1] + wsum[tid][2] + wsum[tid][3];
#pragma unroll
        for (int ks = 0; ks < 4; ks++) {
            uint32_t pa[2][4];
#pragma unroll
            for (int mi = 0; mi < 2; mi++) {
                int arow = wm*32 + mi*16 + (lane & 7) + ((lane >> 3) & 1) * 8;
                int pch  = ks*2 + ((lane >> 4) & 1);
                ldsm4(s_p + aswz(arow, pch), pa[mi]);
            }
#pragma unroll
            for (int ntp = 0; ntp < 2; ntp++) {
                int vrow = ks*16 + (lane & 7) + ((lane >> 3) & 1) * 8;
                int vch  = wn*4 + ntp*2 + ((lane >> 4) & 1);
                uint32_t t4[4];
                ldsm4t(vb + swzh(vrow, vch), t4);
                uint32_t b0[2] = {t4[0], t4[1]}, b1[2] = {t4[2], t4[3]};
#pragma unroll
                for (int mi = 0; mi < 2; mi++) {
                    mma16816(accd[mi][ntp*2],     pa[mi], b0);
                    mma16816(accd[mi][ntp*2 + 1], pa[mi], b1);
                }
            }
        }
        __syncthreads();
        if (ch + 2 <= rb) load_kv(ch + 2);
        CP_COMMIT();
    }

#pragma unroll
    for (int mi = 0; mi < 2; mi++)
#pragma unroll
        for (int ni = 0; ni < 4; ni++) {
            int rowl0 = wm*32 + mi*16 + rl;
            int col   = wn*32 + ni*8 + cl;
#pragma unroll
            for (int rr2 = 0; rr2 < 2; rr2++) {
                int rowl = rowl0 + rr2*8;
                float invl = 1.0f / l_s[rowl];
                __half2 o;
                o.x = __float2half_rn(accd[mi][ni][rr2*2]   * invl);
                o.y = __float2half_rn(accd[mi][ni][rr2*2+1] * invl);
                *(__half2*)(dot + (rowbase + r0 + rowl) * Dd + colbase + col) = o;
            }
        }
}

__device__ void attn_state_body(const __half* __restrict__ sq, const __half* __restrict__ sk,
                                const __half* __restrict__ v, __half* __restrict__ memo,
                                char* sms, int slice)
{
    const uint32_t s_base = smem_u32(sms);
    __shared__ float z_s[128], den_s[64], denk_s[64];

    const int tid = threadIdx.x;
    const int lane = tid & 31;
    const int w = tid >> 5;
    const int wm = w >> 1;
    const int wn = w & 1;
    const int bh = slice >> 1;
    const int half = slice & 1;
    const int dvb = half * 64;
    const int b = bh >> 4, h = bh & 15;
    const int colbase = h * 128;
    const int rl = lane >> 2, cl = (lane & 3) * 2;

    for (int i = tid; i < 4096; i += 256) ((uint32_t*)sms)[i] = 0u;
    if (tid < 128) z_s[tid] = 1.0f / 128.0f;

    auto prefetch = [&](int idx, int buf) {
        const int seg = idx >> 3, rb = idx & 7;
        const size_t rowb = (size_t)(b * Ss + seg * Ll) + rb * 64;
        const uint32_t Bo = s_base + SBUF + buf * SBUFSZ;
#pragma unroll
        for (int t = 0; t < 4; t++) {
            int i2 = tid + t * 256, row = i2 >> 4, c = i2 & 15;
            size_t g = (rowb + row) * Dd + colbase + c * 8;
            cp_async16(Bo + SOFF_SQ + swzh(row, c), sq + g);
            cp_async16(Bo + SOFF_SK + swzh(row, c), sk + g);
        }
#pragma unroll
        for (int t = 0; t < 2; t++) {
            int i2 = tid + t * 256, row = i2 >> 3, c = i2 & 7;
            size_t g = (rowb + row) * Dd + colbase + dvb + c * 8;
            cp_async16(Bo + SOFF_V + aswz(row, c), v + g);
        }
    };

    __syncthreads();
    prefetch(0, 0); CP_COMMIT();
    prefetch(1, 1); CP_COMMIT();

    float upd[2][4][4];
#pragma unroll
    for (int a2 = 0; a2 < 2; a2++)
#pragma unroll
        for (int b2 = 0; b2 < 4; b2++)
#pragma unroll
            for (int c2 = 0; c2 < 4; c2++) upd[a2][b2][c2] = 0.0f;
    float zacc = 0.0f;

    for (int idx = 0; idx < 64; idx++) {
        const int buf = idx & 1;
        const int seg = idx >> 3, rb = idx & 7;
        const size_t rowb = (size_t)(b * Ss + seg * Ll) + rb * 64;
        const uint32_t Bo = s_base + SBUF + buf * SBUFSZ;
        char* Bc = sms + SBUF + buf * SBUFSZ;

        CP_WAIT1();
        __syncthreads();

        {
            int row = tid >> 2, qtr = tid & 3;
            float ds = 0.0f, dk2 = 0.0f;
#pragma unroll
            for (int pi = 0; pi < 16; pi++) {
                int p = qtr * 16 + pi;
                uint32_t off = swzh(row, p >> 2) + (p & 3) * 4;
                __half2 hq = *(__half2*)(Bc + SOFF_SQ + off);
                __half2 hk = *(__half2*)(Bc + SOFF_SK + off);
                float z0 = z_s[2*p], z1 = z_s[2*p + 1];
                ds  += __half2float(hq.x) * z0 + __half2float(hq.y) * z1;
                dk2 += __half2float(hk.x) * z0 + __half2float(hk.y) * z1;
            }
            ds  += __shfl_xor_sync(0xffffffffu, ds, 1);
            ds  += __shfl_xor_sync(0xffffffffu, ds, 2);
            dk2 += __shfl_xor_sync(0xffffffffu, dk2, 1);
            dk2 += __shfl_xor_sync(0xffffffffu, dk2, 2);
            if (qtr == 0) { den_s[row] = ds; denk_s[row] = dk2; }
        }

        float accm[4][4], accv[4][4];
#pragma unroll
        for (int i = 0; i < 4; i++)
#pragma unroll
            for (int j = 0; j < 4; j++) { accm[i][j] = 0.0f; accv[i][j] = 0.0f; }
#pragma unroll
        for (int ks = 0; ks < 8; ks++) {
            uint32_t aq[4], ak[4];
            int arow = wm*16 + (lane & 7) + ((lane >> 3) & 1) * 8;
            int ach  = ks*2 + ((lane >> 4) & 1);
            ldsm4(Bo + SOFF_SQ + swzh(arow, ach), aq);
            ldsm4(Bo + SOFF_SK + swzh(arow, ach), ak);
#pragma unroll
            for (int ntp = 0; ntp < 2; ntp++) {
                int mrow = ks*16 + (lane & 7) + ((lane >> 3) & 1) * 8;
                int mch  = wn*4 + ntp*2 + ((lane >> 4) & 1);
                uint32_t t4[4];
                ldsm4t(s_base + aswz(mrow, mch), t4);
                uint32_t b0[2] = {t4[0], t4[1]}, b1[2] = {t4[2], t4[3]};
                mma16816(accm[ntp*2],     aq, b0);
                mma16816(accm[ntp*2 + 1], aq, b1);
                mma16816(accv[ntp*2],     ak, b0);
                mma16816(accv[ntp*2 + 1], ak, b1);
            }
        }
        __syncthreads();

#pragma unroll
        for (int ni = 0; ni < 4; ni++) {
            int col = wn*32 + ni*8 + cl;
#pragma unroll
            for (int rr2 = 0; rr2 < 2; rr2++) {
                int rowl = wm*16 + rl + rr2*8;
                float invd = 1.0f / den_s[rowl];
                float invk = 1.0f / denk_s[rowl];
                uint32_t soff = aswz(rowl, col >> 3) + (col & 7) * 2;
                __half2 vv = *(__half2*)(Bc + SOFF_V + soff);
                __half2 o, od;
                o.x = __float2half_rn(accm[ni][rr2*2]   * invd);
                o.y = __float2half_rn(accm[ni][rr2*2+1] * invd);
                od.x = __float2half_rn(__half2float(vv.x) - accv[ni][rr2*2]   * invk);
                od.y = __float2half_rn(__half2float(vv.y) - accv[ni][rr2*2+1] * invk);
                *(__half2*)(memo + (rowb + rowl) * Dd + colbase + dvb + col) = o;
                *(__half2*)(Bc + SOFF_V + soff) = od;
            }
        }
        __syncthreads();

#pragma unroll
        for (int ks = 0; ks < 4; ks++) {
            uint32_t a2[2][4];
#pragma unroll
            for (int mt = 0; mt < 2; mt++) {
                int srow = ks*16 + (lane & 7) + ((lane >> 4) & 1) * 8;
                int sch  = wm*4 + mt*2 + ((lane >> 3) & 1);
                ldsm4t(Bo + SOFF_SK + swzh(srow, sch), a2[mt]);
            }
#pragma unroll
            for (int ntp = 0; ntp < 2; ntp++) {
                int vrow = ks*16 + (lane & 7) + ((lane >> 3) & 1) * 8;
                int vch  = wn*4 + ntp*2 + ((lane >> 4) & 1);
                uint32_t t4[4];
                ldsm4t(Bo + SOFF_V + aswz(vrow, vch), t4);
                uint32_t b0[2] = {t4[0], t4[1]}, b1[2] = {t4[2], t4[3]};
#pragma unroll
                for (int mt = 0; mt < 2; mt++) {
                    mma16816(upd[mt][ntp*2],     a2[mt], b0);
                    mma16816(upd[mt][ntp*2 + 1], a2[mt], b1);
                }
            }
        }
        if (tid < 128) {
#pragma unroll 8
            for (int r = 0; r < 64; r++) {
                __half hv = *(__half*)(Bc + SOFF_SK + swzh(r, tid >> 3) + (tid & 7) * 2);
                zacc += __half2float(hv);
            }
        }

        if (rb == 7) {
#pragma unroll
            for (int mt = 0; mt < 2; mt++)
#pragma unroll
                for (int ni = 0; ni < 4; ni++) {
                    int dv = wn*32 + ni*8 + cl;
#pragma unroll
                    for (int rr2 = 0; rr2 < 2; rr2++) {
                        int dk = wm*32 + mt*16 + rl + rr2*8;
                        float2* pf = (float2*)&g_mem32[(size_t)slice * 8192 + dk * 64 + dv];
                        float2 cur;
                        if (seg == 0) {
                            cur.x = upd[mt][ni][rr2*2];
                            cur.y = upd[mt][ni][rr2*2+1];
                        } else {
                            cur = *pf;
                            cur.x += upd[mt][ni][rr2*2];
                            cur.y += upd[mt][ni][rr2*2+1];
                        }
                        *pf = cur;
                        __half2 hm;
                        hm.x = __float2half_rn(cur.x);
                        hm.y = __float2half_rn(cur.y);
                        *(__half2*)(sms + aswz(dk, dv >> 3) + (dv & 7) * 2) = hm;
                        upd[mt][ni][rr2*2] = 0.0f;
                        upd[mt][ni][rr2*2+1] = 0.0f;
                    }
                }
            if (tid < 128) { z_s[tid] += zacc; zacc = 0.0f; }
        }
        __syncthreads();
        if (idx + 2 < 64) prefetch(idx + 2, buf);
        CP_COMMIT();
    }
}

__global__ void __launch_bounds__(256, 2)
attn_fused(const __half* __restrict__ q, const __half* __restrict__ k,
           const __half* __restrict__ v, const __half* __restrict__ sq,
           const __half* __restrict__ sk,
           __half* __restrict__ dot, __half* __restrict__ memo)
{
    extern __shared__ char sma[];
    if (blockIdx.x < 64) {
        attn_state_body(sq, sk, v, memo, sma, blockIdx.x);
    } else {
        int lid = blockIdx.x - 64;
        attn_local_flash(q, k, v, dot, sma, lid & 7, (lid >> 3) & 7, lid >> 6);
    }
}

// ---------------- combine: att = gate*memo + (1-gate)*dot ----------------
__global__ void __launch_bounds__(256)
combine_att(__half* __restrict__ att, const __half* __restrict__ dot,
            const float* __restrict__ betas)
{
    size_t i8 = (size_t)blockIdx.x * 256 + threadIdx.x;
    size_t e0 = i8 * 8;
    int c0 = (int)(e0 & 2047);
    uint4 mu = *(uint4*)(att + e0);
    uint4 du = *(const uint4*)(dot + e0);
    __half* mh = (__half*)&mu;
    __half* dh = (__half*)&du;
    __half out[8];
#pragma unroll
    for (int j = 0; j < 8; j++) {
        float g = 1.0f / (1.0f + __expf(-betas[c0 + j]));
        out[j] = __float2half_rn(g * __half2float(mh[j]) + (1.0f - g) * __half2float(dh[j]));
    }
    *(uint4*)(att + e0) = *(uint4*)out;
}

// ---------------- residual + LayerNorm (float4) ----------------
__global__ void __launch_bounds__(256)
resid_ln(const float* __restrict__ h2, const float* __restrict__ x,
         const float* __restrict__ w, const float* __restrict__ bsh,
         float* __restrict__ out)
{
    __shared__ float ybuf[Dd];
    __shared__ float red[17];
    const int row = blockIdx.x;
    const int tid = threadIdx.x;
    const float4* hr = (const float4*)(h2 + (size_t)row * Dd);
    const float4* xr = (const float4*)(x  + (size_t)row * Dd);

    float s = 0.0f, sq = 0.0f;
#pragma unroll
    for (int t = 0; t < 2; t++) {
        int c4 = tid + t * 256;
        float4 hv = hr[c4], xv = xr[c4];
        float4 yv;
        yv.x = hv.x + xv.x; yv.y = hv.y + xv.y;
        yv.z = hv.z + xv.z; yv.w = hv.w + xv.w;
        *(float4*)&ybuf[c4 * 4] = yv;
        s  += yv.x + yv.y + yv.z + yv.w;
        sq += yv.x*yv.x + yv.y*yv.y + yv.z*yv.z + yv.w*yv.w;
    }
#pragma unroll
    for (int o = 16; o > 0; o >>= 1) {
        s  += __shfl_xor_sync(0xffffffffu, s, o);
        sq += __shfl_xor_sync(0xffffffffu, sq, o);
    }
    int warp = tid >> 5, lane = tid & 31;
    if (lane == 0) { red[warp] = s; red[8 + warp] = sq; }
    __syncthreads();
    if (tid == 0) {
        float S = 0, SQ = 0;
        for (int i = 0; i < 8; i++) { S += red[i]; SQ += red[8 + i]; }
        red[0] = S; red[1] = SQ;
    }
    __syncthreads();
    float mu  = red[0] / (float)Dd;
    float var = red[1] / (float)Dd - mu * mu;
    float inv = rsqrtf(var + 1e-5f);
#pragma unroll
    for (int t = 0; t < 2; t++) {
        int c4 = tid + t * 256;
        float4 yv = *(float4*)&ybuf[c4 * 4];
        float4 wv = *(const float4*)(w + c4 * 4);
        float4 bv = *(const float4*)(bsh + c4 * 4);
        float4 o;
        o.x = (yv.x - mu) * inv * wv.x + bv.x;
        o.y = (yv.y - mu) * inv * wv.y + bv.y;
        o.z = (yv.z - mu) * inv * wv.z + bv.z;
        o.w = (yv.w - mu) * inv * wv.w + bv.w;
        *(float4*)(out + (size_t)row * Dd + c4 * 4) = o;
    }
}

// ---------------- launch ----------------
extern "C" void kernel_launch(void* const* d_in, const int* in_sizes, int n_in,
                              void* d_out, int out_size)
{
    const float* x    = (const float*)d_in[0];
    const float* Wq   = (const float*)d_in[1];
    const float* bq   = (const float*)d_in[2];
    const float* Wk   = (const float*)d_in[3];
    const float* bk   = (const float*)d_in[4];
    const float* Wv   = (const float*)d_in[5];
    const float* bv   = (const float*)d_in[6];
    const float* Wo   = (const float*)d_in[7];
    const float* bo   = (const float*)d_in[8];
    const float* beta = (const float*)d_in[9];
    const float* W1   = (const float*)d_in[10];
    const float* b1   = (const float*)d_in[11];
    const float* W2   = (const float*)d_in[12];
    const float* b2   = (const float*)d_in[13];
    const float* lnw  = (const float*)d_in[14];
    const float* lnb  = (const float*)d_in[15];
    float* out = (float*)d_out;

    float *ph2;
    __half *pxh, *pqh, *pkh, *pvh, *psq, *psk, *pdot, *path, *pah, *ph1h;
    __half *wq, *wk, *wv, *wo, *w1, *w2;
    cudaGetSymbolAddress((void**)&ph2,  g_h2);
    cudaGetSymbolAddress((void**)&pxh,  g_x_h);
    cudaGetSymbolAddress((void**)&pqh,  g_q_h);
    cudaGetSymbolAddress((void**)&pkh,  g_k_h);
    cudaGetSymbolAddress((void**)&pvh,  g_v_h);
    cudaGetSymbolAddress((void**)&psq,  g_sq_h);
    cudaGetSymbolAddress((void**)&psk,  g_sk_h);
    cudaGetSymbolAddress((void**)&pdot, g_dot_h);
    cudaGetSymbolAddress((void**)&path, g_att_h);
    cudaGetSymbolAddress((void**)&pah,  g_a_h);
    cudaGetSymbolAddress((void**)&ph1h, g_h1_h);
    cudaGetSymbolAddress((void**)&wq, g_wq);
    cudaGetSymbolAddress((void**)&wk, g_wk);
    cudaGetSymbolAddress((void**)&wv, g_wv);
    cudaGetSymbolAddress((void**)&wo, g_wo);
    cudaGetSymbolAddress((void**)&w1, g_w1);
    cudaGetSymbolAddress((void**)&w2, g_w2);

    cudaFuncSetAttribute(attn_fused, cudaFuncAttributeMaxDynamicSharedMemorySize, FU_SMEM);
    cudaFuncSetAttribute(gemm_mma<0>, cudaFuncAttributeMaxDynamicSharedMemorySize, GEMM_SMEM_BYTES);
    cudaFuncSetAttribute(gemm_mma<1>, cudaFuncAttributeMaxDynamicSharedMemorySize, GEMM_SMEM_BYTES);
    cudaFuncSetAttribute(gemm_mma<2>, cudaFuncAttributeMaxDynamicSharedMemorySize, GEMM_SMEM_BYTES);
    cudaFuncSetAttribute(gemm_qkv,    cudaFuncAttributeMaxDynamicSharedMemorySize, GEMM_SMEM_BYTES);

    conv_all<<<8192, 256>>>(x, pxh, Wq, Wk, Wv, Wo, W1, W2,                 // 1
                            wq, wk, wv, wo, w1, w2);
    gemm_qkv<<<dim3(48, 64), 256, GEMM_SMEM_BYTES>>>(                       // 2
        pxh, wq, wk, wv, bq, bk, bv, pqh, pkh, pvh, psq, psk, BSr, Dd);

    attn_fused<<<2112, 256, FU_SMEM>>>(pqh, pkh, pvh, psq, psk,             // 3
                                       pdot, path);
    combine_att<<<(BSr * Dd) / 2048, 256>>>(path, pdot, beta);              // 4

    dim3 gP(Dd/128, BSr/128);   // (16, 64)
    gemm_mma<1><<<gP, 256, GEMM_SMEM_BYTES>>>(path, wo, bo, nullptr, pah, BSr, Dd, Dd);   // 5
    dim3 gW1(DH/128, BSr/128);  // (64, 64)
    gemm_mma<2><<<gW1, 256, GEMM_SMEM_BYTES>>>(pah, w1, b1, nullptr, ph1h, BSr, DH, Dd);  // 6
    gemm_mma<0><<<gP, 256, GEMM_SMEM_BYTES>>>(ph1h, w2, b2, ph2, nullptr, BSr, Dd, DH);   // 7

    resid_ln<<<BSr, 256>>>(ph2, x, lnw, lnb, out);                          // 8
}